// round 16
// baseline (speedup 1.0000x reference)
#include <cuda_runtime.h>

#define N_FULL   50000
#define NLAT     10
#define MU       32
#define BATCH    8
#define NODES    32
#define MSTR     33               // m-stride in G/W2
#define ISTR     1058             // i-stride (mod 32 == 2 -> bank gets 2i term)
#define GSZ      (NLAT * ISTR)    // 10580 floats per array
#define TMAIN    512
#define TPREP    512

// smem float offsets (main)
#define OFF_G     0
#define OFF_W2    10580
#define OFF_ENCS  21160            // [10][8] k-major = 80
#define OFF_INV2  21240            // [10][8][32] = 2560
#define OFF_CM    23800            // int[10][32] = 320
#define OFF_CNT   24120            // uint8[10][8][32] = 2560 B = 640 floats
#define OFF_NB    24760            // ushort[1024] = 512 floats
#define SMEM_BYTES ((24760 + 512) * 4)   // 101,088 B -> 2 CTAs/SM

// Scratch (static __device__ arrays: no dynamic allocation allowed)
__device__ float g_encoded[BATCH * NLAT];                 // bias pre-added
__device__ __align__(128) float g_dec4[N_FULL * 16];      // 64B rows [v0..v9,pad6]

// ---------------------------------------------------------------------------
// Kernel 1 (fused, 512 threads): blocks 0..79 compute encoded[b,i]+enc_b[i].
// Blocks 80..177 transpose decoder [n,N] -> [N,16] (64B-aligned rows).
// ---------------------------------------------------------------------------
__global__ void __launch_bounds__(TPREP)
prep_encode_kernel(const float* __restrict__ x,
                   const float* __restrict__ ew,
                   const float* __restrict__ enc_b,
                   const float* __restrict__ decoder) {
    if (blockIdx.x < BATCH * NLAT) {
        const int b = blockIdx.x / NLAT;
        const int i = blockIdx.x % NLAT;
        const float4* xr = (const float4*)(x  + (size_t)b * N_FULL);
        const float4* wr = (const float4*)(ew + (size_t)i * N_FULL);
        float acc = 0.0f;
#pragma unroll 4
        for (int t = threadIdx.x; t < N_FULL / 4; t += TPREP) {
            float4 a = __ldg(xr + t);
            float4 c = __ldg(wr + t);
            acc = fmaf(a.x, c.x, acc);
            acc = fmaf(a.y, c.y, acc);
            acc = fmaf(a.z, c.z, acc);
            acc = fmaf(a.w, c.w, acc);
        }
#pragma unroll
        for (int d = 16; d > 0; d >>= 1)
            acc += __shfl_xor_sync(0xffffffffu, acc, d);
        __shared__ float red[16];
        int lane = threadIdx.x & 31, warp = threadIdx.x >> 5;
        if (lane == 0) red[warp] = acc;
        __syncthreads();
        if (threadIdx.x == 0) {
            float s = 0.0f;
#pragma unroll
            for (int w = 0; w < 16; w++) s += red[w];
            g_encoded[blockIdx.x] = s + __ldg(enc_b + i);   // bias folded in
        }
    } else {
        int p = (blockIdx.x - BATCH * NLAT) * TPREP + threadIdx.x;
        if (p < N_FULL) {
            float v[NLAT];
#pragma unroll
            for (int i = 0; i < NLAT; i++)
                v[i] = __ldg(decoder + (size_t)i * N_FULL + p);
            float4* dst = (float4*)(g_dec4 + (size_t)p * 16);
            dst[0] = make_float4(v[0], v[1], v[2], v[3]);
            dst[1] = make_float4(v[4], v[5], v[6], v[7]);
            dst[2] = make_float4(v[8], v[9], 0.0f, 0.0f);
            dst[3] = make_float4(0.0f, 0.0f, 0.0f, 0.0f);
        }
    }
}

// ---------------------------------------------------------------------------
// Kernel 2: main. 512 threads, 32 nodes/block, 2 CTAs/SM, 4 barriers.
//
//  Entry: NB tile -> smem; warps 0..9 issue their 10 bw LDGs; encS fill.
//  Post-B0 OVERLAP:
//   - warps 10..15: speculative gather chunks 0..35 (rows m<16).
//   - warps 0..9: phase 0 (z; EXACT division-cnt -> sCnt bytes; inv2 ->
//     sInv2; cm[i][j] = max_b cnt), then gather chunks 36..63.
//  B1. Residual gather: rows m in [16, rmax_j), rmax_j = max_i cm (exact,
//      no guard needed: phase C uses the stored cnt).
//  B2. Scan (warps 0..9): fully-unrolled 32-iter prefix of (g, m^2 g);
//      garbage beyond rmax never read (cnt-1 < rmax).
//  B3. Phase C (warps 0..7, b = warp, lane = j): loop i = 0..9 reading
//      sCnt/sInv2/G/W2;
//        smoothed = (Pg[cnt-1] - inv2*Pm2[cnt-1]) / (cnt - inv2*S2(cnt));
//      acc += enc[i,b]*smv; direct STG to out. (P2 + combine + B4 deleted.)
// ---------------------------------------------------------------------------
__global__ void __launch_bounds__(TMAIN, 2)
main_kernel(const float* __restrict__ bw,
            const int*   __restrict__ neigh,
            float*       __restrict__ out) {
    extern __shared__ float sm[];
    float*          G     = sm + OFF_G;
    float*          W2    = sm + OFF_W2;
    float*          encS  = sm + OFF_ENCS;
    float*          sInv2 = sm + OFF_INV2;
    int*            cm    = (int*)(sm + OFF_CM);
    unsigned char*  sCnt  = (unsigned char*)(sm + OFF_CNT);
    unsigned short* NB    = (unsigned short*)(sm + OFF_NB);

    const int tid    = threadIdx.x;
    const int lane   = tid & 31;
    const int warp   = tid >> 5;
    const int p_base = blockIdx.x * NODES;
    const int q  = lane & 3;             // 16B quarter of 64B decoder row
    const int rl = lane >> 2;            // row-in-instruction 0..7

    // ---- entry: NB tile, bw prefetch (warps 0..9), encS ----
    {
        int base = p_base * MU + tid * 2;
        int2 v = make_int2(0, 0);
        if (base + 1 < N_FULL * MU) v = *(const int2*)(neigh + base);
        NB[tid * 2 + 0] = (unsigned short)v.x;
        NB[tid * 2 + 1] = (unsigned short)v.y;
    }
    float bwv[NLAT];
    const int pc = min(p_base + lane, N_FULL - 1);
    if (warp < NLAT) {
#pragma unroll
        for (int k = 0; k < NLAT; k++)
            bwv[k] = __ldg(bw + (size_t)(warp * NLAT + k) * N_FULL + pc);
    }
    if (tid < BATCH * NLAT)              // encS[k*8+b]
        encS[tid] = g_encoded[(tid & 7) * NLAT + (tid >> 3)];
    __syncthreads();                                   // B0

    // ---- overlapped: spec gather (m<16) + phase 0 ----
    if (warp >= NLAT) {
        // warps 10..15: chunks 0..35 (6 each). chunk c: j = c>>1, mb=(c&1)*8
#pragma unroll
        for (int r = 0; r < 6; r++) {
            const int c = (warp - NLAT) * 6 + r;
            const int j = c >> 1;
            const int m = (c & 1) * 8 + rl;
            const int nb = NB[j * MU + m];
            if (q < 3) {
                float4 v = __ldg((const float4*)g_dec4 + nb * 4 + q);
                const int a0 = (4 * q) * ISTR + m * MSTR + j;
                G[a0] = v.x;
                G[a0 + ISTR] = v.y;
                if (q < 2) {
                    G[a0 + 2 * ISTR] = v.z;
                    G[a0 + 3 * ISTR] = v.w;
                }
            }
        }
    } else {
        // warps 0..9: phase 0 (i = warp, j = lane)
        const int i = warp;
        float z[BATCH];
#pragma unroll
        for (int b = 0; b < BATCH; b++) z[b] = 0.0f;
#pragma unroll
        for (int k = 0; k < NLAT; k++) {
            float4 e0 = *(const float4*)(encS + k * 8);      // broadcast LDS
            float4 e1 = *(const float4*)(encS + k * 8 + 4);
            z[0] = fmaf(bwv[k], e0.x, z[0]);
            z[1] = fmaf(bwv[k], e0.y, z[1]);
            z[2] = fmaf(bwv[k], e0.z, z[2]);
            z[3] = fmaf(bwv[k], e0.w, z[3]);
            z[4] = fmaf(bwv[k], e1.x, z[4]);
            z[5] = fmaf(bwv[k], e1.y, z[5]);
            z[6] = fmaf(bwv[k], e1.z, z[6]);
            z[7] = fmaf(bwv[k], e1.w, z[7]);
        }
        int cmax = 0;
#pragma unroll
        for (int b = 0; b < BATCH; b++) {
            float e    = __expf(-z[b]);
            float tt   = 1.0f + e;                              // = 1/w
            float u    = __fdividef((float)MU, tt);             // = MU*w
            int   cnt  = min(MU, (int)u + 1);
            float inv2 = tt * tt * (1.0f / (float)(MU * MU));   // 1/(MU*w)^2
            sInv2[(i * 8 + b) * 32 + lane] = inv2;
            sCnt [(i * 8 + b) * 32 + lane] = (unsigned char)cnt;
            cmax = max(cmax, cnt);
        }
        cm[i * 32 + lane] = cmax;        // exact bound (phase C uses sCnt)

        // then help with remaining spec chunks 36..63 (<=3 rounds)
#pragma unroll
        for (int r = 0; r < 3; r++) {
            const int c = 36 + warp + NLAT * r;
            if (c < 64) {
                const int j = c >> 1;
                const int m = (c & 1) * 8 + rl;
                const int nb = NB[j * MU + m];
                if (q < 3) {
                    float4 v = __ldg((const float4*)g_dec4 + nb * 4 + q);
                    const int a0 = (4 * q) * ISTR + m * MSTR + j;
                    G[a0] = v.x;
                    G[a0 + ISTR] = v.y;
                    if (q < 2) {
                        G[a0 + 2 * ISTR] = v.z;
                        G[a0 + 3 * ISTR] = v.w;
                    }
                }
            }
        }
    }
    __syncthreads();                                   // B1

    // ---- residual gather: rows m in [16, rmax_j), warp = 2 nodes ----
    {
#pragma unroll
        for (int half = 0; half < 2; half++) {
            const int j = warp * 2 + half;
            int rmj = 0;
#pragma unroll
            for (int i = 0; i < NLAT; i++)
                rmj = max(rmj, cm[i * 32 + j]);        // broadcast LDS
            if (rmj > 16) {
#pragma unroll
                for (int t4 = 2; t4 < 4; t4++) {
                    const int m = t4 * 8 + rl;
                    if (m < rmj && q < 3) {
                        const int nb = NB[j * MU + m];
                        float4 v = __ldg((const float4*)g_dec4 + nb * 4 + q);
                        const int a0 = (4 * q) * ISTR + m * MSTR + j;
                        G[a0] = v.x;
                        G[a0 + ISTR] = v.y;
                        if (q < 2) {
                            G[a0 + 2 * ISTR] = v.z;
                            G[a0 + 3 * ISTR] = v.w;
                        }
                    }
                }
            }
        }
    }
    __syncthreads();                                   // B2

    // ---- scan: warps 0..9 (i = warp, j = lane), fully unrolled ----
    if (warp < NLAT) {
        const int base = warp * ISTR + lane;
        float pg = 0.0f, pm = 0.0f;
#pragma unroll
        for (int m = 0; m < MU; m++) {
            float v = G[base + m * MSTR];
            pg += v;
            pm = fmaf((float)(m * m), v, pm);
            G [base + m * MSTR] = pg;
            W2[base + m * MSTR] = pm;
        }
    }
    __syncthreads();                                   // B3

    // ---- phase C: warps 0..7 (b = warp, lane = j), direct output ----
    const int p = p_base + lane;
    if (warp < BATCH && p < N_FULL) {
        const int b = warp, j = lane;
        float acc = 0.0f;
#pragma unroll
        for (int i = 0; i < NLAT; i++) {
            const int   idx  = (i * 8 + b) * 32 + j;
            const float inv2 = sInv2[idx];
            const int   cnt  = (int)sCnt[idx];

            const int base = i * ISTR + (cnt - 1) * MSTR + j;
            float Pg = G[base];
            float Pm = W2[base];
            int   c1 = cnt - 1;
            float S2 = (float)(c1 * cnt * (2 * cnt - 1)) * (1.0f / 6.0f);
            float s  = (float)cnt - inv2 * S2;
            float smv = __fdividef(fmaf(-inv2, Pm, Pg), s);
            acc = fmaf(encS[i * 8 + b], smv, acc);
        }
        out[(size_t)b * N_FULL + p] = acc;
    }
}

// ---------------------------------------------------------------------------
extern "C" void kernel_launch(void* const* d_in, const int* in_sizes, int n_in,
                              void* d_out, int out_size) {
    const float* x       = (const float*)d_in[0];
    const float* enc_w   = (const float*)d_in[1];
    const float* enc_b   = (const float*)d_in[2];
    const float* decoder = (const float*)d_in[3];
    const float* bw      = (const float*)d_in[4];
    const int*   neigh   = (const int*)  d_in[5];
    float*       out     = (float*)d_out;
    (void)in_sizes; (void)n_in; (void)out_size;

    const int tp_blocks = (N_FULL + TPREP - 1) / TPREP;         // 98
    prep_encode_kernel<<<BATCH * NLAT + tp_blocks, TPREP>>>(x, enc_w, enc_b,
                                                            decoder);

    cudaFuncSetAttribute(main_kernel,
                         cudaFuncAttributeMaxDynamicSharedMemorySize,
                         SMEM_BYTES);
    main_kernel<<<(N_FULL + NODES - 1) / NODES, TMAIN, SMEM_BYTES>>>(
        bw, neigh, out);
}